// round 1
// baseline (speedup 1.0000x reference)
#include <cuda_runtime.h>
#include <cuda_bf16.h>

// db4 level-1 DWT low-pass reconstruction.
// x: [B*C rows, L=4096]. out: low (N floats) then high (N floats).
//
// Per row:
//   ca[i]   = sum_m h[m] * X(1+2i-m),  i in [0, 2051),  X = symmetric-ext x
//   low[2k]   = h1*ca[k] + h3*ca[k+1] + h5*ca[k+2] + h7*ca[k+3]
//   low[2k+1] = h0*ca[k] + h2*ca[k+1] + h4*ca[k+2] + h6*ca[k+3]
//   high = x - low

#define ROW_L   4096
#define NCA     2051
#define NTHREADS 256

__device__ __forceinline__ int symidx(int q) {
    // numpy 'symmetric' pad: q<0 -> -q-1 ; q>=L -> 2L-1-q  (pad width 7 << L, single reflection)
    q = (q < 0) ? (-q - 1) : q;
    q = (q >= ROW_L) ? (2 * ROW_L - 1 - q) : q;
    return q;
}

__global__ void __launch_bounds__(NTHREADS)
dwt_db4_kernel(const float* __restrict__ x,
               float* __restrict__ low_out,
               float* __restrict__ high_out)
{
    __shared__ float sx[ROW_L];
    __shared__ float sca[NCA + 1];

    const float h0 = -0.010597401784997278f;
    const float h1 =  0.032883011666982945f;
    const float h2 =  0.030841381835986965f;
    const float h3 = -0.18703481171888114f;
    const float h4 = -0.02798376941698385f;
    const float h5 =  0.6308807679295904f;
    const float h6 =  0.7148465705525415f;
    const float h7 =  0.23037781330885523f;

    const size_t row = blockIdx.x;
    const float* __restrict__ xr = x + row * (size_t)ROW_L;

    // Stage row into shared with float4 loads (coalesced, 16B per lane)
    {
        const float4* __restrict__ x4 = (const float4*)xr;
        float4* sx4 = (float4*)sx;
        #pragma unroll
        for (int t = 0; t < ROW_L / 4 / NTHREADS; ++t) {
            sx4[threadIdx.x + t * NTHREADS] = x4[threadIdx.x + t * NTHREADS];
        }
    }
    __syncthreads();

    // Analysis: stride-2 correlation with symmetric boundary, 2051 coeffs
    for (int i = threadIdx.x; i < NCA; i += NTHREADS) {
        const int b = 2 * i + 1;   // ca[i] taps X(b-m), m=0..7
        float s;
        s = h0 * sx[symidx(b)];
        s = fmaf(h1, sx[symidx(b - 1)], s);
        s = fmaf(h2, sx[symidx(b - 2)], s);
        s = fmaf(h3, sx[symidx(b - 3)], s);
        s = fmaf(h4, sx[symidx(b - 4)], s);
        s = fmaf(h5, sx[symidx(b - 5)], s);
        s = fmaf(h6, sx[symidx(b - 6)], s);
        s = fmaf(h7, sx[symidx(b - 7)], s);
        sca[i] = s;
    }
    __syncthreads();

    // Synthesis + residual; one float2 per output stream per thread-iter
    float2* __restrict__ low2  = (float2*)(low_out  + row * (size_t)ROW_L);
    float2* __restrict__ high2 = (float2*)(high_out + row * (size_t)ROW_L);
    #pragma unroll
    for (int t = 0; t < (ROW_L / 2) / NTHREADS; ++t) {
        const int k = threadIdx.x + t * NTHREADS;   // k in [0, 2048)
        const float c0 = sca[k];
        const float c1 = sca[k + 1];
        const float c2 = sca[k + 2];
        const float c3 = sca[k + 3];

        float le;   // low[2k]
        le = h1 * c0;
        le = fmaf(h3, c1, le);
        le = fmaf(h5, c2, le);
        le = fmaf(h7, c3, le);

        float lo;   // low[2k+1]
        lo = h0 * c0;
        lo = fmaf(h2, c1, lo);
        lo = fmaf(h4, c2, lo);
        lo = fmaf(h6, c3, lo);

        const float xe = sx[2 * k];
        const float xo = sx[2 * k + 1];

        low2[k]  = make_float2(le, lo);
        high2[k] = make_float2(xe - le, xo - lo);
    }
}

extern "C" void kernel_launch(void* const* d_in, const int* in_sizes, int n_in,
                              void* d_out, int out_size)
{
    const float* x = (const float*)d_in[0];
    const int n = in_sizes[0];            // B*C*L = 16*512*4096
    float* low  = (float*)d_out;          // outputs concatenated: (low, high)
    float* high = low + (size_t)n;
    const int rows = n / ROW_L;           // 8192
    dwt_db4_kernel<<<rows, NTHREADS>>>(x, low, high);
}